// round 16
// baseline (speedup 1.0000x reference)
#include <cuda_runtime.h>
#include <cuda_fp16.h>
#include <stdint.h>
#include <math.h>

#define NMAX 100000
#define EMAX 1600000
#define FULL 0xffffffffu

// ---------------- scratch (static device globals; no allocations) ----------
__device__ int      g_count[NMAX];
__device__ int      g_rowstart[NMAX + 1];
__device__ int      g_cursor[NMAX];
__device__ int      g_srcs[EMAX];
__device__ float    g_invdeg[NMAX];
__device__ int      g_bflag[64];
__device__ int      g_bincl[64];
__device__ uint4    g_u[NMAX * 16];    // x @ Wl1, fp16 (128 halves/row)
__device__ uint32_t g_v[NMAX * 64];    // x @ Wr1 + b1, fp16 (128 halves/row)
__device__ uint2    g_hh[NMAX * 32];   // hidden, fp16 (128 halves/row)
__device__ uint4    g_z[NMAX * 8];     // h @ Wl2, fp16 (64 halves/row)
__device__ uint32_t g_pre[NMAX * 32];  // h @ Wr2 + b2, fp16 (64 halves/row)
__device__ uint4    g_w1h[256 * 16];   // [Wl1|Wr1]^T fp16: [n=256][k=128]
__device__ uint4    g_w2h[128 * 16];   // [Wl2|Wr2]^T fp16: [n=128][k=128]

// ---------------- helpers ---------------------------------------------------
__device__ __forceinline__ uint32_t smem_u32(const void* p) {
    uint32_t a;
    asm("{ .reg .u64 t; cvta.to.shared.u64 t, %1; cvt.u32.u64 %0, t; }" : "=r"(a) : "l"(p));
    return a;
}
__device__ __forceinline__ unsigned int packh2(float a, float b) {
    __half2 h = __floats2half2_rn(a, b);
    return *(unsigned int*)&h;
}
__device__ __forceinline__ void acc8(float* a, uint4 w) {
    float2 f0 = __half22float2(*(__half2*)&w.x);
    float2 f1 = __half22float2(*(__half2*)&w.y);
    float2 f2 = __half22float2(*(__half2*)&w.z);
    float2 f3 = __half22float2(*(__half2*)&w.w);
    a[0] += f0.x; a[1] += f0.y; a[2] += f1.x; a[3] += f1.y;
    a[4] += f2.x; a[5] += f2.y; a[6] += f3.x; a[7] += f3.y;
}
__device__ __forceinline__ void accpair(float* a, uint4 w0, uint4 w1) {
    __half2 s0 = __hadd2(*(__half2*)&w0.x, *(__half2*)&w1.x);
    __half2 s1 = __hadd2(*(__half2*)&w0.y, *(__half2*)&w1.y);
    __half2 s2 = __hadd2(*(__half2*)&w0.z, *(__half2*)&w1.z);
    __half2 s3 = __hadd2(*(__half2*)&w0.w, *(__half2*)&w1.w);
    float2 f0 = __half22float2(s0);
    float2 f1 = __half22float2(s1);
    float2 f2 = __half22float2(s2);
    float2 f3 = __half22float2(s3);
    a[0] += f0.x; a[1] += f0.y; a[2] += f1.x; a[3] += f1.y;
    a[4] += f2.x; a[5] += f2.y; a[6] += f3.x; a[7] += f3.y;
}
// 2-level fp16 tree: 4 rows combined in fp16, one fp32 accumulate
__device__ __forceinline__ void accquad(float* a, uint4 w0, uint4 w1, uint4 w2, uint4 w3) {
    __half2 s0 = __hadd2(__hadd2(*(__half2*)&w0.x, *(__half2*)&w1.x),
                         __hadd2(*(__half2*)&w2.x, *(__half2*)&w3.x));
    __half2 s1 = __hadd2(__hadd2(*(__half2*)&w0.y, *(__half2*)&w1.y),
                         __hadd2(*(__half2*)&w2.y, *(__half2*)&w3.y));
    __half2 s2 = __hadd2(__hadd2(*(__half2*)&w0.z, *(__half2*)&w1.z),
                         __hadd2(*(__half2*)&w2.z, *(__half2*)&w3.z));
    __half2 s3 = __hadd2(__hadd2(*(__half2*)&w0.w, *(__half2*)&w1.w),
                         __hadd2(*(__half2*)&w2.w, *(__half2*)&w3.w));
    float2 f0 = __half22float2(s0);
    float2 f1 = __half22float2(s1);
    float2 f2 = __half22float2(s2);
    float2 f3 = __half22float2(s3);
    a[0] += f0.x; a[1] += f0.y; a[2] += f1.x; a[3] += f1.y;
    a[4] += f2.x; a[5] += f2.y; a[6] += f3.x; a[7] += f3.y;
}

#define LDSM4(r, addr)                                                                \
    asm volatile("ldmatrix.sync.aligned.m8n8.x4.shared.b16 {%0,%1,%2,%3}, [%4];"      \
        : "=r"((r)[0]), "=r"((r)[1]), "=r"((r)[2]), "=r"((r)[3]) : "r"(addr))

#define MMA16816(d, a, b0, b1)                                                        \
    asm volatile("mma.sync.aligned.m16n8k16.row.col.f32.f16.f16.f32 "                 \
        "{%0,%1,%2,%3}, {%4,%5,%6,%7}, {%8,%9}, {%0,%1,%2,%3};"                       \
        : "+f"((d)[0]), "+f"((d)[1]), "+f"((d)[2]), "+f"((d)[3])                      \
        : "r"((a)[0]), "r"((a)[1]), "r"((a)[2]), "r"((a)[3]), "r"(b0), "r"(b1))

// ---------------- fused: histogram (int4) + weight convert ------------------
__global__ void k_histcvt(const int4* __restrict__ dst4, int e4, int rem, int hb,
                          const int* __restrict__ dst,
                          const float* __restrict__ Wl1, const float* __restrict__ Wr1,
                          const float* __restrict__ Wl2, const float* __restrict__ Wr2)
{
    const int bid = blockIdx.x;
    if (bid < hb) {
        int i = bid * 256 + threadIdx.x;
        if (i < e4) {
            int4 d = __ldg(&dst4[i]);
            atomicAdd(&g_count[d.x], 1);
            atomicAdd(&g_count[d.y], 1);
            atomicAdd(&g_count[d.z], 1);
            atomicAdd(&g_count[d.w], 1);
        }
        if (i < rem) atomicAdd(&g_count[dst[e4 * 4 + i]], 1);
    } else {
        int i = (bid - hb) * 256 + threadIdx.x;
        __half* w1 = (__half*)g_w1h;
        __half* w2 = (__half*)g_w2h;
        if (i < 256 * 128) {
            int nn = i >> 7, k = i & 127;
            float v = (nn < 128) ? Wl1[k * 128 + nn] : Wr1[k * 128 + (nn - 128)];
            w1[i] = __float2half_rn(v);
        } else if (i < 256 * 128 + 128 * 128) {
            int j = i - 256 * 128;
            int nn = j >> 7, k = j & 127;
            float v = (nn < 64) ? Wl2[k * 64 + nn] : Wr2[k * 64 + (nn - 64)];
            w2[j] = __float2half_rn(v);
        }
    }
}

__global__ void k_scanfill(int n, int e) {
    const int tid = threadIdx.x;
    const int lane = tid & 31, wid = tid >> 5;
    const int b = blockIdx.x;
    const int gbase = b * 2048 + tid * 4;
    int c[4];
    int s = 0;
#pragma unroll
    for (int j = 0; j < 4; j++) {
        c[j] = (gbase + j < n) ? g_count[gbase + j] : 0;
        s += c[j];
    }
    int incl = s;
#pragma unroll
    for (int off = 1; off < 32; off <<= 1) {
        int t = __shfl_up_sync(FULL, incl, off);
        if (lane >= off) incl += t;
    }
    __shared__ int wsum[16];
    __shared__ int sprev;
    if (lane == 31) wsum[wid] = incl;
    __syncthreads();
    if (tid < 16) {
        int v = wsum[tid];
#pragma unroll
        for (int off = 1; off < 16; off <<= 1) {
            int t = __shfl_up_sync(0xffffu, v, off);
            if (tid >= off) v += t;
        }
        wsum[tid] = v;
    }
    __syncthreads();
    if (tid == 0) {
        int prev = 0;
        if (b > 0) {
            while (atomicAdd(&g_bflag[b - 1], 0) == 0) {}
            prev = atomicAdd(&g_bincl[b - 1], 0);
        }
        g_bincl[b] = prev + wsum[15];
        __threadfence();
        atomicExch(&g_bflag[b], 1);
        sprev = prev;
        if (b == 0) g_rowstart[n] = e;
    }
    __syncthreads();
    int base = sprev + (incl - s) + (wid ? wsum[wid - 1] : 0);
#pragma unroll
    for (int j = 0; j < 4; j++) {
        if (gbase + j < n) {
            g_rowstart[gbase + j] = base;
            g_cursor[gbase + j] = base;
            g_invdeg[gbase + j] = 1.0f / fmaxf((float)c[j], 1.0f);
            base += c[j];
        }
    }
}

// ---------------- fused: scatter + mma.sync GEMM 1 (A staged once) ----------
#define SCAT_BLOCKS 1024
#define XP_SMEM (34816 + 34816)
__global__ __launch_bounds__(256, 3)
void k_scatxproj(const float* __restrict__ x, const float* __restrict__ bias,
                 uint32_t* __restrict__ u32, uint32_t* __restrict__ v32, int n,
                 const int* __restrict__ src, const int* __restrict__ dst,
                 int e, int ntiles)
{
    extern __shared__ char smem[];
    const int tid = threadIdx.x;

    if ((int)blockIdx.x >= ntiles) {
        const int sb = blockIdx.x - ntiles;
        for (int i = sb * 256 + tid; i < e; i += SCAT_BLOCKS * 256) {
            int pos = atomicAdd(&g_cursor[dst[i]], 1);
            g_srcs[pos] = src[i];
        }
        return;
    }

    const uint32_t sbA = smem_u32(smem);
    const uint32_t sbB = sbA + 34816;
    const int wid = tid >> 5, lane = tid & 31;
    const int row0T = blockIdx.x * 128;

    {
        uint4* sA4 = (uint4*)smem;
        const float4* x4 = (const float4*)x;
        for (int i = tid; i < 2048; i += 256) {
            int r = i >> 4, hc = i & 15;
            int gr = row0T + r;
            uint4 val = make_uint4(0, 0, 0, 0);
            if (gr < n) {
                float4 f0 = __ldg(&x4[gr * 32 + hc * 2]);
                float4 f1 = __ldg(&x4[gr * 32 + hc * 2 + 1]);
                val = make_uint4(packh2(f0.x, f0.y), packh2(f0.z, f0.w),
                                 packh2(f1.x, f1.y), packh2(f1.z, f1.w));
            }
            sA4[r * 17 + hc] = val;
        }
    }

    const int wm = wid & 3, wn = wid >> 2;
    const int gid = lane >> 2, tig = lane & 3;
    const uint32_t aRow = (uint32_t)(wm * 32 + (lane & 15));
    const uint32_t aColOff = 8u * (lane >> 4);
    const uint32_t bRow = (uint32_t)(wn * 64 + (lane & 7) + 8 * (lane >> 4));
    const uint32_t bColOff = 8u * ((lane >> 3) & 1);
    const uint4* wt = (const uint4*)g_w1h;
    uint4* sB4 = (uint4*)(smem + 34816);

#pragma unroll 1
    for (int q = 0; q < 2; q++) {
        for (int i = tid; i < 2048; i += 256) {
            int r = i >> 4, hc = i & 15;
            sB4[r * 17 + hc] = __ldg(&wt[(q * 128 + r) * 16 + hc]);
        }
        __syncthreads();

        float acc[2][8][4];
#pragma unroll
        for (int mt = 0; mt < 2; mt++)
#pragma unroll
            for (int nt = 0; nt < 8; nt++)
#pragma unroll
                for (int qq = 0; qq < 4; qq++) acc[mt][nt][qq] = 0.f;

#pragma unroll
        for (int k0 = 0; k0 < 8; k0++) {
            const uint32_t kk = (uint32_t)k0 * 16;
            uint32_t a[2][4];
#pragma unroll
            for (int mt = 0; mt < 2; mt++) {
                uint32_t addr = sbA + ((aRow + mt * 16) * 136 + kk + aColOff) * 2;
                LDSM4(a[mt], addr);
            }
#pragma unroll
            for (int np = 0; np < 4; np++) {
                uint32_t addr = sbB + ((bRow + np * 16) * 136 + kk + bColOff) * 2;
                uint32_t b[4];
                LDSM4(b, addr);
#pragma unroll
                for (int mt = 0; mt < 2; mt++) {
                    MMA16816(acc[mt][np * 2],     a[mt], b[0], b[1]);
                    MMA16816(acc[mt][np * 2 + 1], a[mt], b[2], b[3]);
                }
            }
        }
        __syncthreads();

#pragma unroll
        for (int mt = 0; mt < 2; mt++) {
            int r0 = row0T + wm * 32 + mt * 16 + gid;
            int r1 = r0 + 8;
            const int cb = wn * 32;
            if (q == 0) {
#pragma unroll
                for (int nt = 0; nt < 8; nt++) {
                    if (r0 < n) u32[r0 * 64 + cb + nt * 4 + tig] = packh2(acc[mt][nt][0], acc[mt][nt][1]);
                    if (r1 < n) u32[r1 * 64 + cb + nt * 4 + tig] = packh2(acc[mt][nt][2], acc[mt][nt][3]);
                }
            } else {
                const float2* b2 = (const float2*)bias;
#pragma unroll
                for (int nt = 0; nt < 8; nt++) {
                    float2 bb = __ldg(&b2[cb + nt * 4 + tig]);
                    if (r0 < n) v32[r0 * 64 + cb + nt * 4 + tig] =
                        packh2(acc[mt][nt][0] + bb.x, acc[mt][nt][1] + bb.y);
                    if (r1 < n) v32[r1 * 64 + cb + nt * 4 + tig] =
                        packh2(acc[mt][nt][2] + bb.x, acc[mt][nt][3] + bb.y);
                }
            }
        }
    }
}

// ---------------- mma.sync GEMM 2: [z | pre] = h @ [Wl2 | Wr2] --------------
#define ZP_SMEM (34816 + 34816)
__global__ __launch_bounds__(256, 3)
void mma_zp(const float* __restrict__ bias,
            uint32_t* __restrict__ z32, uint32_t* __restrict__ pre32, int n)
{
    extern __shared__ char smem[];
    const uint32_t sbA = smem_u32(smem);
    const uint32_t sbB = sbA + 34816;
    const int tid = threadIdx.x, wid = tid >> 5, lane = tid & 31;
    const int row0T = blockIdx.x * 128;

    {
        const uint4* wt = (const uint4*)g_w2h;
        uint4* sB4 = (uint4*)(smem + 34816);
        for (int i = tid; i < 2048; i += 256) {
            int r = i >> 4, hc = i & 15;
            sB4[r * 17 + hc] = __ldg(&wt[r * 16 + hc]);
        }
    }
    {
        uint4* sA4 = (uint4*)smem;
        const uint4* h16 = (const uint4*)g_hh;
        for (int i = tid; i < 2048; i += 256) {
            int r = i >> 4, hc = i & 15;
            int gr = row0T + r;
            uint4 val = make_uint4(0, 0, 0, 0);
            if (gr < n) val = __ldg(&h16[gr * 16 + hc]);
            sA4[r * 17 + hc] = val;
        }
    }
    __syncthreads();

    const int wm = wid & 3, gq = wid >> 2;
    const int gid = lane >> 2, tig = lane & 3;

    float acc[2][8][4];
#pragma unroll
    for (int mt = 0; mt < 2; mt++)
#pragma unroll
        for (int nt = 0; nt < 8; nt++)
#pragma unroll
            for (int qq = 0; qq < 4; qq++) acc[mt][nt][qq] = 0.f;

    const uint32_t aRow = (uint32_t)(wm * 32 + (lane & 15));
    const uint32_t aColOff = 8u * (lane >> 4);
    const uint32_t bRow = (uint32_t)(gq * 64 + (lane & 7) + 8 * (lane >> 4));
    const uint32_t bColOff = 8u * ((lane >> 3) & 1);

#pragma unroll
    for (int k0 = 0; k0 < 8; k0++) {
        const uint32_t kk = (uint32_t)k0 * 16;
        uint32_t a[2][4];
#pragma unroll
        for (int mt = 0; mt < 2; mt++) {
            uint32_t addr = sbA + ((aRow + mt * 16) * 136 + kk + aColOff) * 2;
            LDSM4(a[mt], addr);
        }
#pragma unroll
        for (int np = 0; np < 4; np++) {
            uint32_t addr = sbB + ((bRow + np * 16) * 136 + kk + bColOff) * 2;
            uint32_t b[4];
            LDSM4(b, addr);
#pragma unroll
            for (int mt = 0; mt < 2; mt++) {
                MMA16816(acc[mt][np * 2],     a[mt], b[0], b[1]);
                MMA16816(acc[mt][np * 2 + 1], a[mt], b[2], b[3]);
            }
        }
    }

#pragma unroll
    for (int mt = 0; mt < 2; mt++) {
        int r0 = row0T + wm * 32 + mt * 16 + gid;
        int r1 = r0 + 8;
        if (gq == 0) {
#pragma unroll
            for (int nt = 0; nt < 8; nt++) {
                if (r0 < n) z32[r0 * 32 + nt * 4 + tig] = packh2(acc[mt][nt][0], acc[mt][nt][1]);
                if (r1 < n) z32[r1 * 32 + nt * 4 + tig] = packh2(acc[mt][nt][2], acc[mt][nt][3]);
            }
        } else {
            const float2* b2 = (const float2*)bias;
#pragma unroll
            for (int nt = 0; nt < 8; nt++) {
                float2 bb = __ldg(&b2[nt * 4 + tig]);
                if (r0 < n) pre32[r0 * 32 + nt * 4 + tig] =
                    packh2(acc[mt][nt][0] + bb.x, acc[mt][nt][1] + bb.y);
                if (r1 < n) pre32[r1 * 32 + nt * 4 + tig] =
                    packh2(acc[mt][nt][2] + bb.x, acc[mt][nt][3] + bb.y);
            }
        }
    }
}

// ---------------- fused: h = fp16(relu(mean_agg(u_fp16) + v_fp16)) ----------
// warp per node; pair split, 8 neighbors/iter via 2-level fp16 tree.
__global__ void k_aggrelu(const uint4* __restrict__ u, const uint2* __restrict__ v,
                          uint2* __restrict__ hh, int n)
{
    int node = blockIdx.x * (blockDim.x >> 5) + (threadIdx.x >> 5);
    if (node >= n) return;
    const int lane = threadIdx.x & 31;
    const int pair = lane >> 4, c = lane & 15;
    const int beg = g_rowstart[node];
    const int cnt = g_rowstart[node + 1] - beg;

    float a0[8] = {0,0,0,0,0,0,0,0};

    for (int base = 0; base < cnt; base += 32) {
        const int m = min(32, cnt - base);
        int idx = (lane < m) ? __ldg(&g_srcs[beg + base + lane]) : 0;
        int j = 0;
        for (; j + 7 < m; j += 8) {
            int s0 = __shfl_sync(FULL, idx, j + pair);
            int s1 = __shfl_sync(FULL, idx, j + 2 + pair);
            int s2 = __shfl_sync(FULL, idx, j + 4 + pair);
            int s3 = __shfl_sync(FULL, idx, j + 6 + pair);
            uint4 w0 = __ldg(&u[s0 * 16 + c]);
            uint4 w1 = __ldg(&u[s1 * 16 + c]);
            uint4 w2 = __ldg(&u[s2 * 16 + c]);
            uint4 w3 = __ldg(&u[s3 * 16 + c]);
            accquad(a0, w0, w1, w2, w3);
        }
        for (; j + 3 < m; j += 4) {
            int s0 = __shfl_sync(FULL, idx, j + pair);
            int s1 = __shfl_sync(FULL, idx, j + 2 + pair);
            uint4 w0 = __ldg(&u[s0 * 16 + c]);
            uint4 w1 = __ldg(&u[s1 * 16 + c]);
            accpair(a0, w0, w1);
        }
        for (; j < m; j += 2) {
            int s0 = __shfl_sync(FULL, idx, (j + pair) & 31);
            if (j + pair < m) {
                uint4 w0 = __ldg(&u[s0 * 16 + c]);
                acc8(a0, w0);
            }
        }
    }
#pragma unroll
    for (int i = 0; i < 8; i++)
        a0[i] += __shfl_xor_sync(FULL, a0[i], 16);

    const float inv = g_invdeg[node];
    uint2 vv = __ldg(&v[node * 32 + c * 2 + pair]);
    float2 v0 = __half22float2(*(__half2*)&vv.x);
    float2 v1 = __half22float2(*(__half2*)&vv.y);
    const int k0 = pair * 4;
    float r0 = fmaxf(a0[k0 + 0] * inv + v0.x, 0.f);
    float r1 = fmaxf(a0[k0 + 1] * inv + v0.y, 0.f);
    float r2 = fmaxf(a0[k0 + 2] * inv + v1.x, 0.f);
    float r3 = fmaxf(a0[k0 + 3] * inv + v1.y, 0.f);
    hh[node * 32 + c * 2 + pair] = make_uint2(packh2(r0, r1), packh2(r2, r3));
}

// ---------------- fused: out = log_softmax(mean_agg(z_fp16) + pre_fp16) -----
// warp per node; quad split, 16 neighbors/iter via 2-level fp16 tree.
__global__ void k_agg64out(const uint4* __restrict__ z, const uint4* __restrict__ pre,
                           float4* __restrict__ out, int n)
{
    int node = blockIdx.x * (blockDim.x >> 5) + (threadIdx.x >> 5);
    if (node >= n) return;
    const int lane = threadIdx.x & 31;
    const int quad = lane >> 3, c = lane & 7;
    const int beg = g_rowstart[node];
    const int cnt = g_rowstart[node + 1] - beg;

    float a0[8] = {0,0,0,0,0,0,0,0};

    for (int base = 0; base < cnt; base += 32) {
        const int m = min(32, cnt - base);
        int idx = (lane < m) ? __ldg(&g_srcs[beg + base + lane]) : 0;
        int j = 0;
        for (; j + 15 < m; j += 16) {
            int s0 = __shfl_sync(FULL, idx, j + quad);
            int s1 = __shfl_sync(FULL, idx, j + 4 + quad);
            int s2 = __shfl_sync(FULL, idx, j + 8 + quad);
            int s3 = __shfl_sync(FULL, idx, j + 12 + quad);
            uint4 w0 = __ldg(&z[s0 * 8 + c]);
            uint4 w1 = __ldg(&z[s1 * 8 + c]);
            uint4 w2 = __ldg(&z[s2 * 8 + c]);
            uint4 w3 = __ldg(&z[s3 * 8 + c]);
            accquad(a0, w0, w1, w2, w3);
        }
        for (; j + 7 < m; j += 8) {
            int s0 = __shfl_sync(FULL, idx, j + quad);
            int s1 = __shfl_sync(FULL, idx, j + 4 + quad);
            uint4 w0 = __ldg(&z[s0 * 8 + c]);
            uint4 w1 = __ldg(&z[s1 * 8 + c]);
            accpair(a0, w0, w1);
        }
        for (; j < m; j += 4) {
            int s0 = __shfl_sync(FULL, idx, (j + quad) & 31);
            if (j + quad < m) {
                uint4 w0 = __ldg(&z[s0 * 8 + c]);
                acc8(a0, w0);
            }
        }
    }
#pragma unroll
    for (int i = 0; i < 8; i++) {
        a0[i] += __shfl_xor_sync(FULL, a0[i], 8);
        a0[i] += __shfl_xor_sync(FULL, a0[i], 16);
    }
    const float inv = g_invdeg[node];
    uint4 pp = __ldg(&pre[node * 8 + c]);
    float2 p0 = __half22float2(*(__half2*)&pp.x);
    float2 p1 = __half22float2(*(__half2*)&pp.y);
    float2 p2 = __half22float2(*(__half2*)&pp.z);
    float2 p3 = __half22float2(*(__half2*)&pp.w);
    float vv[8];
    vv[0] = a0[0] * inv + p0.x; vv[1] = a0[1] * inv + p0.y;
    vv[2] = a0[2] * inv + p1.x; vv[3] = a0[3] * inv + p1.y;
    vv[4] = a0[4] * inv + p2.x; vv[5] = a0[5] * inv + p2.y;
    vv[6] = a0[6] * inv + p3.x; vv[7] = a0[7] * inv + p3.y;

    float m8 = vv[0];
#pragma unroll
    for (int i = 1; i < 8; i++) m8 = fmaxf(m8, vv[i]);
#pragma unroll
    for (int off = 4; off > 0; off >>= 1) m8 = fmaxf(m8, __shfl_xor_sync(FULL, m8, off));
    float s = 0.f;
#pragma unroll
    for (int i = 0; i < 8; i++) s += expf(vv[i] - m8);
#pragma unroll
    for (int off = 4; off > 0; off >>= 1) s += __shfl_xor_sync(FULL, s, off);
    float lse = m8 + logf(s);

    if (quad < 2) {
        const int k0 = quad * 4;
        out[node * 16 + c * 2 + quad] =
            make_float4(vv[k0 + 0] - lse, vv[k0 + 1] - lse,
                        vv[k0 + 2] - lse, vv[k0 + 3] - lse);
    }
}

// ---------------- launch -----------------------------------------------------
extern "C" void kernel_launch(void* const* d_in, const int* in_sizes, int n_in,
                              void* d_out, int out_size)
{
    const float* x   = (const float*)d_in[0];
    const int*   ei  = (const int*)d_in[1];
    const float* Wl1 = (const float*)d_in[2];
    const float* Wr1 = (const float*)d_in[3];
    const float* b1  = (const float*)d_in[4];
    const float* Wl2 = (const float*)d_in[5];
    const float* Wr2 = (const float*)d_in[6];
    const float* b2  = (const float*)d_in[7];
    float* out = (float*)d_out;

    const int n = in_sizes[0] / 128;
    const int e = in_sizes[1] / 2;
    const int* src = ei;
    const int* dst = ei + e;
    const int ntiles = (n + 127) / 128;

    static bool attr_done = false;
    if (!attr_done) {
        cudaFuncSetAttribute(k_scatxproj, cudaFuncAttributeMaxDynamicSharedMemorySize, XP_SMEM);
        cudaFuncSetAttribute(mma_zp,      cudaFuncAttributeMaxDynamicSharedMemorySize, ZP_SMEM);
        attr_done = true;
    }

    void *p_cnt = nullptr, *p_flag = nullptr;
    void *p_u = nullptr, *p_v = nullptr, *p_hh = nullptr, *p_z = nullptr, *p_pre = nullptr;
    cudaGetSymbolAddress(&p_cnt, g_count);
    cudaGetSymbolAddress(&p_flag, g_bflag);
    cudaGetSymbolAddress(&p_u, g_u);
    cudaGetSymbolAddress(&p_v, g_v);
    cudaGetSymbolAddress(&p_hh, g_hh);
    cudaGetSymbolAddress(&p_z, g_z);
    cudaGetSymbolAddress(&p_pre, g_pre);

    const int B = (n + 2047) / 2048;
    const int e4 = e / 4;
    const int rem = e - e4 * 4;
    const int hb = (e4 + 255) / 256;

    cudaMemsetAsync(p_cnt, 0, (size_t)n * sizeof(int));
    cudaMemsetAsync(p_flag, 0, 64 * sizeof(int));

    // launch 1: histogram (int4) + weight convert
    k_histcvt<<<hb + 192, 256>>>((const int4*)dst, e4, rem, hb, dst,
                                 Wl1, Wr1, Wl2, Wr2);
    // launch 2: scan + fill
    k_scanfill<<<B, 512>>>(n, e);
    // launch 3: scatter + x-projection GEMM (A staged once)
    k_scatxproj<<<ntiles + SCAT_BLOCKS, 256, XP_SMEM>>>(
        x, b1, (uint32_t*)p_u, (uint32_t*)p_v, n, src, dst, e, ntiles);
    // launch 4 (ncu-captured): fused aggregation + relu (tree version)
    k_aggrelu<<<(n + 7) / 8, 256>>>((const uint4*)p_u, (const uint2*)p_v,
                                    (uint2*)p_hh, n);
    // launch 5: layer-2 projections
    mma_zp<<<ntiles, 256, ZP_SMEM>>>(b2, (uint32_t*)p_z, (uint32_t*)p_pre, n);
    // launch 6: fused aggregation + log_softmax (tree version)
    k_agg64out<<<(n + 7) / 8, 256>>>((const uint4*)p_z, (const uint4*)p_pre,
                                     (float4*)out, n);
}